// round 8
// baseline (speedup 1.0000x reference)
#include <cuda_runtime.h>
#include <cuda_bf16.h>
#include <cuda_fp8.h>
#include <cstdint>

#define SCALE_F 0.08838834764831845f
#define SW128(x) ((x) ^ (((x) >> 3) & 0x70))

// ---------------- scratch ----------------
__device__ uint8_t       g_Xf8[4096 * 1024];        // X e4m3 [n][d]
__device__ uint8_t       g_Wt8[24 * 128 * 1024];    // W e4m3 transposed [g][e][d]
__device__ uint8_t       g_Qf8[8 * 4096 * 128];     // Q e4m3 [h][n][e]
__device__ uint8_t       g_Kf8[8 * 4096 * 128];     // K e4m3 [h][m][e]
__device__ float         g_Vf[8 * 4096 * 128];      // V f32  [h][m][e]
__device__ __nv_bfloat16 g_Vs[8 * 4096 * 128];      // V/colsum bf16
__device__ float         g_colsum[8 * 4096];
__device__ __nv_bfloat16 g_Pt[8ull * 4096 * 4096];  // P^T = exp(scale*S)[h][m][n]

// ---------------- helpers ----------------
__device__ __forceinline__ uint32_t smem_u32(const void* p) {
    return (uint32_t)__cvta_generic_to_shared(p);
}
__device__ __forceinline__ uint32_t pack_bf2(float lo, float hi) {
    __nv_bfloat162 p = __floats2bfloat162_rn(lo, hi);
    return *reinterpret_cast<uint32_t*>(&p);
}
__device__ __forceinline__ float sigmoidf_(float x) { return 1.0f / (1.0f + __expf(-x)); }
__device__ __forceinline__ uint16_t f8x2(float a, float b) {
    return (uint16_t)__nv_cvt_float2_to_fp8x2(make_float2(a, b), __NV_SATFINITE, __NV_E4M3);
}

#define CPA16(s, g) asm volatile("cp.async.cg.shared.global [%0], [%1], 16;" :: "r"(s), "l"(g))
#define CP_COMMIT() asm volatile("cp.async.commit_group;" ::: "memory")
#define CP_WAIT1()  asm volatile("cp.async.wait_group 1;" ::: "memory")

__device__ __forceinline__ void ldsm4(uint32_t a, uint32_t& r0, uint32_t& r1, uint32_t& r2, uint32_t& r3) {
    asm volatile("ldmatrix.sync.aligned.m8n8.x4.shared.b16 {%0,%1,%2,%3}, [%4];"
                 : "=r"(r0), "=r"(r1), "=r"(r2), "=r"(r3) : "r"(a));
}
__device__ __forceinline__ void ldsm4t(uint32_t a, uint32_t& r0, uint32_t& r1, uint32_t& r2, uint32_t& r3) {
    asm volatile("ldmatrix.sync.aligned.m8n8.x4.trans.shared.b16 {%0,%1,%2,%3}, [%4];"
                 : "=r"(r0), "=r"(r1), "=r"(r2), "=r"(r3) : "r"(a));
}
__device__ __forceinline__ void mma16816(float c[4], uint32_t a0, uint32_t a1, uint32_t a2, uint32_t a3,
                                         uint32_t b0, uint32_t b1) {
    asm volatile("mma.sync.aligned.m16n8k16.row.col.f32.bf16.bf16.f32 "
        "{%0,%1,%2,%3},{%4,%5,%6,%7},{%8,%9},{%0,%1,%2,%3};"
        : "+f"(c[0]), "+f"(c[1]), "+f"(c[2]), "+f"(c[3])
        : "r"(a0), "r"(a1), "r"(a2), "r"(a3), "r"(b0), "r"(b1));
}
__device__ __forceinline__ void mma_f8(float c[4], uint32_t a0, uint32_t a1, uint32_t a2, uint32_t a3,
                                       uint32_t b0, uint32_t b1) {
    asm volatile("mma.sync.aligned.m16n8k32.row.col.f32.e4m3.e4m3.f32 "
        "{%0,%1,%2,%3},{%4,%5,%6,%7},{%8,%9},{%0,%1,%2,%3};"
        : "+f"(c[0]), "+f"(c[1]), "+f"(c[2]), "+f"(c[3])
        : "r"(a0), "r"(a1), "r"(a2), "r"(a3), "r"(b0), "r"(b1));
}

// fp8 swizzled tile (rows x 128B) ldmatrix addressing: kk = 32-byte k-step
__device__ __forceinline__ uint32_t lmA8(uint32_t base, int r0, int kk, int lane) {
    int r = r0 + (lane & 7) + ((lane >> 3) & 1) * 8;
    int c16 = kk * 2 + (lane >> 4);
    return base + SW128((uint32_t)((r << 7) + (c16 << 4)));
}
__device__ __forceinline__ uint32_t lmB8(uint32_t base, int r0, int kk, int lane) {
    int r = r0 + (lane & 7) + (lane >> 4) * 8;
    int c16 = kk * 2 + ((lane >> 3) & 1);
    return base + SW128((uint32_t)((r << 7) + (c16 << 4)));
}
// bf16 linear tile (ld elems): pattern A (B-frags via trans)
__device__ __forceinline__ uint32_t lm_addrA(uint32_t base, int ld, int row0, int col0, int lane) {
    int r = row0 + (lane & 7) + ((lane >> 3) & 1) * 8;
    int c = col0 + (lane >> 4) * 8;
    return base + (uint32_t)(r * ld + c) * 2u;
}
// bf16 linear tile: pattern B (A-frags from [k][n] storage via trans)
__device__ __forceinline__ uint32_t lm_addrB(uint32_t base, int ld, int row0, int col0, int lane) {
    int r = row0 + (lane & 7) + (lane >> 4) * 8;
    int c = col0 + ((lane >> 3) & 1) * 8;
    return base + (uint32_t)(r * ld + c) * 2u;
}

// loaders (256-thread CTAs)
__device__ __forceinline__ void cpa8(uint32_t dst, const uint8_t* src, int ldb, int rows, int tid) {
    for (int o = tid; o < rows * 8; o += 256) {
        int r = o >> 3, c = o & 7;
        CPA16(dst + SW128((uint32_t)((r << 7) + (c << 4))), src + (size_t)r * ldb + c * 16);
    }
}
// 64 x 128 bf16, global row stride ldel elems -> smem 272B rows
__device__ __forceinline__ void cpaB(uint32_t dst, const __nv_bfloat16* src, int ldel, int tid) {
    for (int o = tid; o < 1024; o += 256) {
        int r = o >> 4, c = o & 15;
        CPA16(dst + (uint32_t)(r * 272 + c * 16), (const char*)(src + (size_t)r * ldel) + c * 16);
    }
}
// 64 x 64 bf16, global row stride ldel elems -> smem 144B rows
__device__ __forceinline__ void cpaV64(uint32_t dst, const __nv_bfloat16* src, int ldel, int tid) {
    for (int o = tid; o < 512; o += 256) {
        int r = o >> 3, c = o & 7;
        CPA16(dst + (uint32_t)(r * 144 + c * 16), (const char*)(src + (size_t)r * ldel) + c * 16);
    }
}

// ---------------- cvt X -> fp8 (+ zero colsum) ----------------
__global__ void cvtX_kernel(const float* __restrict__ X) {
    int st = gridDim.x * blockDim.x;
    for (int o = blockIdx.x * blockDim.x + threadIdx.x; o < 1048576; o += st) {
        float4 v = ((const float4*)X)[o];
        ((uint32_t*)g_Xf8)[o] = (uint32_t)f8x2(v.x, v.y) | ((uint32_t)f8x2(v.z, v.w) << 16);
    }
    for (int o = blockIdx.x * blockDim.x + threadIdx.x; o < 32768; o += st)
        g_colsum[o] = 0.f;
}

// ---------------- cvt W -> fp8 transposed [g][e][d] ----------------
__global__ __launch_bounds__(256) void cvtW_kernel(const float* __restrict__ Wq,
                                                   const float* __restrict__ Wk,
                                                   const float* __restrict__ Wv) {
    __shared__ uint8_t t[64][96];
    const int g = blockIdx.z, d0 = blockIdx.x * 64, e0 = blockIdx.y * 64;
    const float* W = (g < 8 ? Wq : g < 16 ? Wk : Wv) + (size_t)(g & 7) * 131072;
    for (int o = threadIdx.x; o < 1024; o += 256) {
        int i = o >> 4, j4 = (o & 15) * 4;
        float4 v = *(const float4*)&W[(size_t)(d0 + i) * 128 + e0 + j4];
        t[j4 + 0][i] = (uint8_t)__nv_cvt_float_to_fp8(v.x, __NV_SATFINITE, __NV_E4M3);
        t[j4 + 1][i] = (uint8_t)__nv_cvt_float_to_fp8(v.y, __NV_SATFINITE, __NV_E4M3);
        t[j4 + 2][i] = (uint8_t)__nv_cvt_float_to_fp8(v.z, __NV_SATFINITE, __NV_E4M3);
        t[j4 + 3][i] = (uint8_t)__nv_cvt_float_to_fp8(v.w, __NV_SATFINITE, __NV_E4M3);
    }
    __syncthreads();
    for (int o = threadIdx.x; o < 256; o += 256) {
        int r = o >> 2, c = (o & 3) * 16;
        *(uint4*)&g_Wt8[(size_t)g * 131072 + (size_t)(e0 + r) * 1024 + d0 + c] = *(uint4*)&t[r][c];
    }
}

// ---------------- proj: C = X @ W_g + b (fp8 mma, k=1024) ----------------
#define PJ_A(b) ((b) * 16384)
#define PJ_B(b) (32768 + (b) * 16384)
__global__ __launch_bounds__(256, 2) void proj_kernel(const float* __restrict__ bq,
                                                      const float* __restrict__ bk,
                                                      const float* __restrict__ bv) {
    extern __shared__ char sm[];
    const uint32_t sb = smem_u32(sm);
    const int g = blockIdx.y, n0 = blockIdx.x * 128;
    const int tid = threadIdx.x, lane = tid & 31, warp = tid >> 5;
    const uint8_t* Xp = g_Xf8 + (size_t)n0 * 1024;
    const uint8_t* Wp = g_Wt8 + (size_t)g * 131072;
    cpa8(sb + PJ_A(0), Xp, 1024, 128, tid);
    cpa8(sb + PJ_B(0), Wp, 1024, 128, tid);
    CP_COMMIT();
    cpa8(sb + PJ_A(1), Xp + 128, 1024, 128, tid);
    cpa8(sb + PJ_B(1), Wp + 128, 1024, 128, tid);
    CP_COMMIT();
    float acc[16][4];
#pragma unroll
    for (int t = 0; t < 16; t++) { acc[t][0] = acc[t][1] = acc[t][2] = acc[t][3] = 0.f; }
    for (int i = 0; i < 8; i++) {
        const int b = i & 1;
        CP_WAIT1();
        __syncthreads();
#pragma unroll
        for (int kk = 0; kk < 4; kk++) {
            uint32_t a0, a1, a2, a3;
            ldsm4(lmA8(sb + PJ_A(b), warp * 16, kk, lane), a0, a1, a2, a3);
#pragma unroll
            for (int nt = 0; nt < 8; nt++) {
                uint32_t b0, b1, b2, b3;
                ldsm4(lmB8(sb + PJ_B(b), nt * 16, kk, lane), b0, b1, b2, b3);
                mma_f8(acc[2 * nt], a0, a1, a2, a3, b0, b1);
                mma_f8(acc[2 * nt + 1], a0, a1, a2, a3, b2, b3);
            }
        }
        __syncthreads();
        if (i < 6) {
            cpa8(sb + PJ_A(b), Xp + (i + 2) * 128, 1024, 128, tid);
            cpa8(sb + PJ_B(b), Wp + (i + 2) * 128, 1024, 128, tid);
        }
        CP_COMMIT();
    }
    const int h = g & 7, qkv = g >> 3;
    const float* bias = (qkv == 0 ? bq : qkv == 1 ? bk : bv) + h * 128;
#pragma unroll
    for (int t = 0; t < 16; t++) {
        int col = t * 8 + (lane & 3) * 2, row = n0 + warp * 16 + (lane >> 2);
        float v0 = acc[t][0] + bias[col], v1 = acc[t][1] + bias[col + 1];
        float v2 = acc[t][2] + bias[col], v3 = acc[t][3] + bias[col + 1];
        int o0 = (h * 4096 + row) * 128 + col, o1 = (h * 4096 + row + 8) * 128 + col;
        if (qkv == 0) {
            *(uint16_t*)&g_Qf8[o0] = f8x2(v0, v1); *(uint16_t*)&g_Qf8[o1] = f8x2(v2, v3);
        } else if (qkv == 1) {
            *(uint16_t*)&g_Kf8[o0] = f8x2(v0, v1); *(uint16_t*)&g_Kf8[o1] = f8x2(v2, v3);
        } else {
            *(float2*)&g_Vf[o0] = make_float2(v0, v1); *(float2*)&g_Vf[o1] = make_float2(v2, v3);
        }
    }
}

// ---- scoreP: m-tile 64, grid 512. warps = 4(m) x 2(n-half). ----
// S'[m][n] = K.Q^T fp8; P=exp -> g_Pt; colsum via 2 commutative atomics/row.
#define CS_K 0
#define CS_Q(b) (8192 + (b) * 16384)
__global__ __launch_bounds__(256, 3) void scoreP_kernel() {
    extern __shared__ char sm[];
    const uint32_t sb = smem_u32(sm);
    const int h = blockIdx.y, m0 = blockIdx.x * 64;
    const int tid = threadIdx.x, lane = tid & 31, warp = tid >> 5;
    const int wm = warp & 3, nh = warp >> 2;
    const uint8_t* K = g_Kf8 + (size_t)h * 524288 + (size_t)m0 * 128;
    const uint8_t* Q = g_Qf8 + (size_t)h * 524288;
    cpa8(sb + CS_K, K, 128, 64, tid);
    cpa8(sb + CS_Q(0), Q, 128, 128, tid);
    CP_COMMIT();
    cpa8(sb + CS_Q(1), Q + 16384, 128, 128, tid);
    CP_COMMIT();
    CP_WAIT1();
    __syncthreads();
    uint32_t kf[4][4];                // persistent K fragments (this warp's 16 m-rows)
#pragma unroll
    for (int kk = 0; kk < 4; kk++)
        ldsm4(lmA8(sb + CS_K, wm * 16, kk, lane), kf[kk][0], kf[kk][1], kf[kk][2], kf[kk][3]);
    float rs0 = 0.f, rs1 = 0.f;
    const size_t pr = (size_t)h * 16777216 + (size_t)(m0 + wm * 16 + (lane >> 2)) * 4096
                      + (size_t)(nh * 64 + (lane & 3) * 2);
    for (int i = 0; i < 32; i++) {
        const int b = i & 1;
        CP_WAIT1();
        __syncthreads();
        float sacc[8][4];
#pragma unroll
        for (int t = 0; t < 8; t++) { sacc[t][0] = sacc[t][1] = sacc[t][2] = sacc[t][3] = 0.f; }
#pragma unroll
        for (int kk = 0; kk < 4; kk++) {
#pragma unroll
            for (int nt = 0; nt < 4; nt++) {
                uint32_t b0, b1, b2, b3;
                ldsm4(lmB8(sb + CS_Q(b), nh * 64 + nt * 16, kk, lane), b0, b1, b2, b3);
                mma_f8(sacc[2 * nt], kf[kk][0], kf[kk][1], kf[kk][2], kf[kk][3], b0, b1);
                mma_f8(sacc[2 * nt + 1], kf[kk][0], kf[kk][1], kf[kk][2], kf[kk][3], b2, b3);
            }
        }
        const size_t pb = pr + (size_t)i * 128;
#pragma unroll
        for (int t = 0; t < 8; t++) {
            float e0 = __expf(sacc[t][0] * SCALE_F), e1 = __expf(sacc[t][1] * SCALE_F);
            float e2 = __expf(sacc[t][2] * SCALE_F), e3 = __expf(sacc[t][3] * SCALE_F);
            rs0 += e0 + e1;
            rs1 += e2 + e3;
            *(uint32_t*)&g_Pt[pb + t * 8]            = pack_bf2(e0, e1);
            *(uint32_t*)&g_Pt[pb + 8 * 4096 + t * 8] = pack_bf2(e2, e3);
        }
        __syncthreads();
        if (i < 30) cpa8(sb + CS_Q(b), Q + (size_t)(i + 2) * 16384, 128, 128, tid);
        CP_COMMIT();
    }
    rs0 += __shfl_xor_sync(0xffffffffu, rs0, 1);
    rs0 += __shfl_xor_sync(0xffffffffu, rs0, 2);
    rs1 += __shfl_xor_sync(0xffffffffu, rs1, 1);
    rs1 += __shfl_xor_sync(0xffffffffu, rs1, 2);
    if ((lane & 3) == 0) {
        int r = m0 + wm * 16 + (lane >> 2);
        atomicAdd(&g_colsum[h * 4096 + r], rs0);
        atomicAdd(&g_colsum[h * 4096 + r + 8], rs1);
    }
}

// ---------------- scalev: Vs = V / colsum (bf16) ----------------
__global__ void scalev_kernel() {
    int st = gridDim.x * blockDim.x;
    for (int i = blockIdx.x * blockDim.x + threadIdx.x; i < 8 * 4096 * 128; i += st) {
        int hm = i >> 7;
        g_Vs[i] = __float2bfloat16(__fdividef(g_Vf[i], g_colsum[hm]));
    }
}

// ---- pv: n-tile 64, grid 512. warps = 4(n) x 2(e). Z = Pt^T @ Vs; sigmoid ----
#define PV_P(b) ((b) * 9216)
#define PV_V(b) (18432 + (b) * 17408)
__global__ __launch_bounds__(256, 3) void pv_kernel(float* __restrict__ out) {
    extern __shared__ char sm[];
    const uint32_t sb = smem_u32(sm);
    const int h = blockIdx.y, n0 = blockIdx.x * 64;
    const int tid = threadIdx.x, lane = tid & 31, warp = tid >> 5;
    const int wn = warp & 3, we = warp >> 2;
    const __nv_bfloat16* P = g_Pt + (size_t)h * 16777216 + n0;   // rows m (stride 4096)
    const __nv_bfloat16* V = g_Vs + (size_t)h * 524288;          // rows m (stride 128)
    cpaV64(sb + PV_P(0), P, 4096, tid);
    cpaB(sb + PV_V(0), V, 128, tid);
    CP_COMMIT();
    cpaV64(sb + PV_P(1), P + (size_t)64 * 4096, 4096, tid);
    cpaB(sb + PV_V(1), V + 64 * 128, 128, tid);
    CP_COMMIT();
    float zacc[8][4];
#pragma unroll
    for (int t = 0; t < 8; t++) { zacc[t][0] = zacc[t][1] = zacc[t][2] = zacc[t][3] = 0.f; }
    for (int i = 0; i < 64; i++) {
        const int b = i & 1;
        CP_WAIT1();
        __syncthreads();
#pragma unroll
        for (int kk = 0; kk < 4; kk++) {
            uint32_t a0, a1, a2, a3;   // A-frags: P^T (warp's 16 n-rows, k=m) from [m][n] tile
            ldsm4t(lm_addrB(sb + PV_P(b), 72, kk * 16, wn * 16, lane), a0, a1, a2, a3);
#pragma unroll
            for (int et = 0; et < 4; et++) {
                uint32_t b0, b1, b2, b3;
                ldsm4t(lm_addrA(sb + PV_V(b), 136, kk * 16, we * 64 + et * 16, lane), b0, b1, b2, b3);
                mma16816(zacc[2 * et], a0, a1, a2, a3, b0, b1);
                mma16816(zacc[2 * et + 1], a0, a1, a2, a3, b2, b3);
            }
        }
        __syncthreads();
        if (i < 62) {
            cpaV64(sb + PV_P(b), P + (size_t)(i + 2) * 64 * 4096, 4096, tid);
            cpaB(sb + PV_V(b), V + (size_t)(i + 2) * 64 * 128, 128, tid);
        }
        CP_COMMIT();
    }
#pragma unroll
    for (int t = 0; t < 8; t++) {
        int col = h * 128 + we * 64 + t * 8 + (lane & 3) * 2;
        int row = n0 + wn * 16 + (lane >> 2);
        *(float2*)&out[(size_t)row * 1024 + col] =
            make_float2(sigmoidf_(zacc[t][0]), sigmoidf_(zacc[t][1]));
        *(float2*)&out[(size_t)(row + 8) * 1024 + col] =
            make_float2(sigmoidf_(zacc[t][2]), sigmoidf_(zacc[t][3]));
    }
}

// ---------------- launch ----------------
extern "C" void kernel_launch(void* const* d_in, const int* in_sizes, int n_in,
                              void* d_out, int out_size) {
    const float* X  = (const float*)d_in[0];
    const float* Wq = (const float*)d_in[1];
    const float* bq = (const float*)d_in[2];
    const float* Wk = (const float*)d_in[3];
    const float* bk = (const float*)d_in[4];
    const float* Wv = (const float*)d_in[5];
    const float* bv = (const float*)d_in[6];
    float* out = (float*)d_out;

    cudaFuncSetAttribute(proj_kernel, cudaFuncAttributeMaxDynamicSharedMemorySize, 65536);
    cudaFuncSetAttribute(scoreP_kernel, cudaFuncAttributeMaxDynamicSharedMemorySize, 40960);
    cudaFuncSetAttribute(pv_kernel, cudaFuncAttributeMaxDynamicSharedMemorySize, 53248);

    cvtX_kernel<<<1024, 256>>>(X);
    cvtW_kernel<<<dim3(16, 2, 24), 256>>>(Wq, Wk, Wv);
    proj_kernel<<<dim3(32, 24), 256, 65536>>>(bq, bk, bv);
    scoreP_kernel<<<dim3(64, 8), 256, 40960>>>();
    scalev_kernel<<<2048, 256>>>();
    pv_kernel<<<dim3(64, 8), 256, 53248>>>(out);
}

// round 9
// speedup vs baseline: 1.0210x; 1.0210x over previous
#include <cuda_runtime.h>
#include <cuda_bf16.h>
#include <cuda_fp8.h>
#include <cstdint>

#define SCALE_F 0.08838834764831845f
#define SW128(x) ((x) ^ (((x) >> 3) & 0x70))

// ---------------- scratch ----------------
__device__ uint8_t       g_Xf8[4096 * 1024];        // X e4m3 [n][d]
__device__ uint8_t       g_Wt8[24 * 128 * 1024];    // W e4m3 transposed [g][e][d]
__device__ uint8_t       g_Qf8[8 * 4096 * 128];     // Q e4m3 [h][n][e]
__device__ uint8_t       g_Kf8[8 * 4096 * 128];     // K e4m3 [h][m][e]
__device__ float         g_Vf[8 * 4096 * 128];      // V f32  [h][m][e]
__device__ __nv_bfloat16 g_Vs[8 * 4096 * 128];      // V/colsum bf16
__device__ __nv_bfloat16 g_Pt[8ull * 4096 * 4096];  // P^T = exp(scale*S)[h][m][n]

// ---------------- helpers ----------------
__device__ __forceinline__ uint32_t smem_u32(const void* p) {
    return (uint32_t)__cvta_generic_to_shared(p);
}
__device__ __forceinline__ uint32_t pack_bf2(float lo, float hi) {
    __nv_bfloat162 p = __floats2bfloat162_rn(lo, hi);
    return *reinterpret_cast<uint32_t*>(&p);
}
__device__ __forceinline__ float sigmoidf_(float x) { return 1.0f / (1.0f + __expf(-x)); }
__device__ __forceinline__ uint16_t f8x2(float a, float b) {
    return (uint16_t)__nv_cvt_float2_to_fp8x2(make_float2(a, b), __NV_SATFINITE, __NV_E4M3);
}

#define CPA16(s, g) asm volatile("cp.async.cg.shared.global [%0], [%1], 16;" :: "r"(s), "l"(g))
#define CP_COMMIT() asm volatile("cp.async.commit_group;" ::: "memory")
#define CP_WAIT1()  asm volatile("cp.async.wait_group 1;" ::: "memory")
#define CP_WAIT2()  asm volatile("cp.async.wait_group 2;" ::: "memory")

__device__ __forceinline__ void ldsm4(uint32_t a, uint32_t& r0, uint32_t& r1, uint32_t& r2, uint32_t& r3) {
    asm volatile("ldmatrix.sync.aligned.m8n8.x4.shared.b16 {%0,%1,%2,%3}, [%4];"
                 : "=r"(r0), "=r"(r1), "=r"(r2), "=r"(r3) : "r"(a));
}
__device__ __forceinline__ void ldsm4t(uint32_t a, uint32_t& r0, uint32_t& r1, uint32_t& r2, uint32_t& r3) {
    asm volatile("ldmatrix.sync.aligned.m8n8.x4.trans.shared.b16 {%0,%1,%2,%3}, [%4];"
                 : "=r"(r0), "=r"(r1), "=r"(r2), "=r"(r3) : "r"(a));
}
__device__ __forceinline__ void mma16816(float c[4], uint32_t a0, uint32_t a1, uint32_t a2, uint32_t a3,
                                         uint32_t b0, uint32_t b1) {
    asm volatile("mma.sync.aligned.m16n8k16.row.col.f32.bf16.bf16.f32 "
        "{%0,%1,%2,%3},{%4,%5,%6,%7},{%8,%9},{%0,%1,%2,%3};"
        : "+f"(c[0]), "+f"(c[1]), "+f"(c[2]), "+f"(c[3])
        : "r"(a0), "r"(a1), "r"(a2), "r"(a3), "r"(b0), "r"(b1));
}
__device__ __forceinline__ void mma_f8(float c[4], uint32_t a0, uint32_t a1, uint32_t a2, uint32_t a3,
                                       uint32_t b0, uint32_t b1) {
    asm volatile("mma.sync.aligned.m16n8k32.row.col.f32.e4m3.e4m3.f32 "
        "{%0,%1,%2,%3},{%4,%5,%6,%7},{%8,%9},{%0,%1,%2,%3};"
        : "+f"(c[0]), "+f"(c[1]), "+f"(c[2]), "+f"(c[3])
        : "r"(a0), "r"(a1), "r"(a2), "r"(a3), "r"(b0), "r"(b1));
}

// fp8 swizzled tile (rows x 128B) ldmatrix addressing: kk = 32-byte k-step
__device__ __forceinline__ uint32_t lmA8(uint32_t base, int r0, int kk, int lane) {
    int r = r0 + (lane & 7) + ((lane >> 3) & 1) * 8;
    int c16 = kk * 2 + (lane >> 4);
    return base + SW128((uint32_t)((r << 7) + (c16 << 4)));
}
__device__ __forceinline__ uint32_t lmB8(uint32_t base, int r0, int kk, int lane) {
    int r = r0 + (lane & 7) + (lane >> 4) * 8;
    int c16 = kk * 2 + ((lane >> 3) & 1);
    return base + SW128((uint32_t)((r << 7) + (c16 << 4)));
}
// bf16 linear tile (ld elems): pattern A (B-frags via trans)
__device__ __forceinline__ uint32_t lm_addrA(uint32_t base, int ld, int row0, int col0, int lane) {
    int r = row0 + (lane & 7) + ((lane >> 3) & 1) * 8;
    int c = col0 + (lane >> 4) * 8;
    return base + (uint32_t)(r * ld + c) * 2u;
}
// bf16 linear tile: pattern B (A-frags from [k][n] storage via trans)
__device__ __forceinline__ uint32_t lm_addrB(uint32_t base, int ld, int row0, int col0, int lane) {
    int r = row0 + (lane & 7) + (lane >> 4) * 8;
    int c = col0 + ((lane >> 3) & 1) * 8;
    return base + (uint32_t)(r * ld + c) * 2u;
}

// loaders (256-thread CTAs)
__device__ __forceinline__ void cpa8(uint32_t dst, const uint8_t* src, int ldb, int rows, int tid) {
    for (int o = tid; o < rows * 8; o += 256) {
        int r = o >> 3, c = o & 7;
        CPA16(dst + SW128((uint32_t)((r << 7) + (c << 4))), src + (size_t)r * ldb + c * 16);
    }
}
// 64 x 128 bf16, global row stride ldel elems -> smem 272B rows
__device__ __forceinline__ void cpaB(uint32_t dst, const __nv_bfloat16* src, int ldel, int tid) {
    for (int o = tid; o < 1024; o += 256) {
        int r = o >> 4, c = o & 15;
        CPA16(dst + (uint32_t)(r * 272 + c * 16), (const char*)(src + (size_t)r * ldel) + c * 16);
    }
}

// ---------------- cvt X -> fp8 ----------------
__global__ void cvtX_kernel(const float* __restrict__ X) {
    int st = gridDim.x * blockDim.x;
    for (int o = blockIdx.x * blockDim.x + threadIdx.x; o < 1048576; o += st) {
        float4 v = ((const float4*)X)[o];
        ((uint32_t*)g_Xf8)[o] = (uint32_t)f8x2(v.x, v.y) | ((uint32_t)f8x2(v.z, v.w) << 16);
    }
}

// ---------------- cvt W -> fp8 transposed [g][e][d] ----------------
__global__ __launch_bounds__(256) void cvtW_kernel(const float* __restrict__ Wq,
                                                   const float* __restrict__ Wk,
                                                   const float* __restrict__ Wv) {
    __shared__ uint8_t t[64][96];
    const int g = blockIdx.z, d0 = blockIdx.x * 64, e0 = blockIdx.y * 64;
    const float* W = (g < 8 ? Wq : g < 16 ? Wk : Wv) + (size_t)(g & 7) * 131072;
    for (int o = threadIdx.x; o < 1024; o += 256) {
        int i = o >> 4, j4 = (o & 15) * 4;
        float4 v = *(const float4*)&W[(size_t)(d0 + i) * 128 + e0 + j4];
        t[j4 + 0][i] = (uint8_t)__nv_cvt_float_to_fp8(v.x, __NV_SATFINITE, __NV_E4M3);
        t[j4 + 1][i] = (uint8_t)__nv_cvt_float_to_fp8(v.y, __NV_SATFINITE, __NV_E4M3);
        t[j4 + 2][i] = (uint8_t)__nv_cvt_float_to_fp8(v.z, __NV_SATFINITE, __NV_E4M3);
        t[j4 + 3][i] = (uint8_t)__nv_cvt_float_to_fp8(v.w, __NV_SATFINITE, __NV_E4M3);
    }
    __syncthreads();
    for (int o = threadIdx.x; o < 256; o += 256) {
        int r = o >> 2, c = (o & 3) * 16;
        *(uint4*)&g_Wt8[(size_t)g * 131072 + (size_t)(e0 + r) * 1024 + d0 + c] = *(uint4*)&t[r][c];
    }
}

// ---------------- proj: C = X @ W_g + b (fp8 mma, k=1024) ----------------
#define PJ_A(b) ((b) * 16384)
#define PJ_B(b) (32768 + (b) * 16384)
__global__ __launch_bounds__(256, 2) void proj_kernel(const float* __restrict__ bq,
                                                      const float* __restrict__ bk,
                                                      const float* __restrict__ bv) {
    extern __shared__ char sm[];
    const uint32_t sb = smem_u32(sm);
    const int g = blockIdx.y, n0 = blockIdx.x * 128;
    const int tid = threadIdx.x, lane = tid & 31, warp = tid >> 5;
    const uint8_t* Xp = g_Xf8 + (size_t)n0 * 1024;
    const uint8_t* Wp = g_Wt8 + (size_t)g * 131072;
    cpa8(sb + PJ_A(0), Xp, 1024, 128, tid);
    cpa8(sb + PJ_B(0), Wp, 1024, 128, tid);
    CP_COMMIT();
    cpa8(sb + PJ_A(1), Xp + 128, 1024, 128, tid);
    cpa8(sb + PJ_B(1), Wp + 128, 1024, 128, tid);
    CP_COMMIT();
    float acc[16][4];
#pragma unroll
    for (int t = 0; t < 16; t++) { acc[t][0] = acc[t][1] = acc[t][2] = acc[t][3] = 0.f; }
    for (int i = 0; i < 8; i++) {
        const int b = i & 1;
        CP_WAIT1();
        __syncthreads();
#pragma unroll
        for (int kk = 0; kk < 4; kk++) {
            uint32_t a0, a1, a2, a3;
            ldsm4(lmA8(sb + PJ_A(b), warp * 16, kk, lane), a0, a1, a2, a3);
#pragma unroll
            for (int nt = 0; nt < 8; nt++) {
                uint32_t b0, b1, b2, b3;
                ldsm4(lmB8(sb + PJ_B(b), nt * 16, kk, lane), b0, b1, b2, b3);
                mma_f8(acc[2 * nt], a0, a1, a2, a3, b0, b1);
                mma_f8(acc[2 * nt + 1], a0, a1, a2, a3, b2, b3);
            }
        }
        __syncthreads();
        if (i < 6) {
            cpa8(sb + PJ_A(b), Xp + (i + 2) * 128, 1024, 128, tid);
            cpa8(sb + PJ_B(b), Wp + (i + 2) * 128, 1024, 128, tid);
        }
        CP_COMMIT();
    }
    const int h = g & 7, qkv = g >> 3;
    const float* bias = (qkv == 0 ? bq : qkv == 1 ? bk : bv) + h * 128;
#pragma unroll
    for (int t = 0; t < 16; t++) {
        int col = t * 8 + (lane & 3) * 2, row = n0 + warp * 16 + (lane >> 2);
        float v0 = acc[t][0] + bias[col], v1 = acc[t][1] + bias[col + 1];
        float v2 = acc[t][2] + bias[col], v3 = acc[t][3] + bias[col + 1];
        int o0 = (h * 4096 + row) * 128 + col, o1 = (h * 4096 + row + 8) * 128 + col;
        if (qkv == 0) {
            *(uint16_t*)&g_Qf8[o0] = f8x2(v0, v1); *(uint16_t*)&g_Qf8[o1] = f8x2(v2, v3);
        } else if (qkv == 1) {
            *(uint16_t*)&g_Kf8[o0] = f8x2(v0, v1); *(uint16_t*)&g_Kf8[o1] = f8x2(v2, v3);
        } else {
            *(float2*)&g_Vf[o0] = make_float2(v0, v1); *(float2*)&g_Vf[o1] = make_float2(v2, v3);
        }
    }
}

// ---- scoreP: m-tile 128, grid (32,8). S'[m][n]=K.Q^T fp8; P=exp -> g_Pt bf16.
// CTA owns its 128 m-rows -> complete colsum at loop end -> writes Vs = V/colsum
// directly (scalev folded). Triple-buffered Q stream.
#define CS_K 0
#define CS_Q(b) (16384 + (b) * 16384)
#define CS_CS 65536
__global__ __launch_bounds__(256, 3) void scoreP_kernel() {
    extern __shared__ char sm[];
    const uint32_t sb = smem_u32(sm);
    float* cs = (float*)(sm + CS_CS);
    const int h = blockIdx.y, m0 = blockIdx.x * 128;
    const int tid = threadIdx.x, lane = tid & 31, warp = tid >> 5;
    const uint8_t* K = g_Kf8 + (size_t)h * 524288 + (size_t)m0 * 128;
    const uint8_t* Q = g_Qf8 + (size_t)h * 524288;
    cpa8(sb + CS_K, K, 128, 128, tid);
    cpa8(sb + CS_Q(0), Q, 128, 128, tid);
    CP_COMMIT();
    cpa8(sb + CS_Q(1), Q + 16384, 128, 128, tid);
    CP_COMMIT();
    cpa8(sb + CS_Q(2), Q + 32768, 128, 128, tid);
    CP_COMMIT();
    CP_WAIT2();                       // K + Q0 landed
    __syncthreads();
    uint32_t kf[4][4];                // persistent K fragments (warp's 16 m-rows)
#pragma unroll
    for (int kk = 0; kk < 4; kk++)
        ldsm4(lmA8(sb + CS_K, warp * 16, kk, lane), kf[kk][0], kf[kk][1], kf[kk][2], kf[kk][3]);
    float rs0 = 0.f, rs1 = 0.f;
    const size_t pr = (size_t)h * 16777216 + (size_t)(m0 + warp * 16 + (lane >> 2)) * 4096
                      + (size_t)((lane & 3) * 2);
    int b = 0;
    for (int i = 0; i < 32; i++) {
        CP_WAIT2();
        __syncthreads();
#pragma unroll
        for (int hf = 0; hf < 2; hf++) {
            float sacc[8][4];
#pragma unroll
            for (int t = 0; t < 8; t++) { sacc[t][0] = sacc[t][1] = sacc[t][2] = sacc[t][3] = 0.f; }
#pragma unroll
            for (int kk = 0; kk < 4; kk++) {
#pragma unroll
                for (int nt = 0; nt < 4; nt++) {
                    uint32_t b0, b1, b2, b3;
                    ldsm4(lmB8(sb + CS_Q(b), hf * 64 + nt * 16, kk, lane), b0, b1, b2, b3);
                    mma_f8(sacc[2 * nt], kf[kk][0], kf[kk][1], kf[kk][2], kf[kk][3], b0, b1);
                    mma_f8(sacc[2 * nt + 1], kf[kk][0], kf[kk][1], kf[kk][2], kf[kk][3], b2, b3);
                }
            }
            const size_t pb = pr + (size_t)i * 128 + hf * 64;
#pragma unroll
            for (int t = 0; t < 8; t++) {
                float e0 = __expf(sacc[t][0] * SCALE_F), e1 = __expf(sacc[t][1] * SCALE_F);
                float e2 = __expf(sacc[t][2] * SCALE_F), e3 = __expf(sacc[t][3] * SCALE_F);
                rs0 += e0 + e1;
                rs1 += e2 + e3;
                *(uint32_t*)&g_Pt[pb + t * 8]            = pack_bf2(e0, e1);
                *(uint32_t*)&g_Pt[pb + 8 * 4096 + t * 8] = pack_bf2(e2, e3);
            }
        }
        __syncthreads();
        if (i < 29) cpa8(sb + CS_Q(b), Q + (size_t)(i + 3) * 16384, 128, 128, tid);
        CP_COMMIT();
        b = (b == 2) ? 0 : b + 1;
    }
    // colsum (complete for this CTA's m-rows) -> smem
    rs0 += __shfl_xor_sync(0xffffffffu, rs0, 1);
    rs0 += __shfl_xor_sync(0xffffffffu, rs0, 2);
    rs1 += __shfl_xor_sync(0xffffffffu, rs1, 1);
    rs1 += __shfl_xor_sync(0xffffffffu, rs1, 2);
    if ((lane & 3) == 0) {
        cs[warp * 16 + (lane >> 2)]     = rs0;
        cs[warp * 16 + 8 + (lane >> 2)] = rs1;
    }
    __syncthreads();
    // fused scalev: Vs[m][e] = V[m][e] / colsum[m] (bf16)
    for (int o = tid; o < 4096; o += 256) {
        int row = o >> 5, e4 = (o & 31) * 4;
        size_t gi = (size_t)(h * 4096 + m0 + row) * 128 + e4;
        float4 v = *(const float4*)&g_Vf[gi];
        float inv = __frcp_rn(cs[row]);
        uint2 u;
        u.x = pack_bf2(v.x * inv, v.y * inv);
        u.y = pack_bf2(v.z * inv, v.w * inv);
        *(uint2*)&g_Vs[gi] = u;
    }
}

// ---- pv (R6 shape): n-tile 128, full e. Z[n][e] = sum_m Pt[m][n]*Vs[m][e]; sigmoid ----
#define PV_P(b) ((b) * 17408)
#define PV_V(b) (34816 + (b) * 17408)
__global__ __launch_bounds__(256, 2) void pv_kernel(float* __restrict__ out) {
    extern __shared__ char sm[];
    const uint32_t sb = smem_u32(sm);
    const int h = blockIdx.y, n0 = blockIdx.x * 128;
    const int tid = threadIdx.x, lane = tid & 31, warp = tid >> 5;
    const __nv_bfloat16* P = g_Pt + (size_t)h * 16777216 + n0;   // rows m (stride 4096)
    const __nv_bfloat16* V = g_Vs + (size_t)h * 524288;          // rows m (stride 128)
    cpaB(sb + PV_P(0), P, 4096, tid);
    cpaB(sb + PV_V(0), V, 128, tid);
    CP_COMMIT();
    cpaB(sb + PV_P(1), P + (size_t)64 * 4096, 4096, tid);
    cpaB(sb + PV_V(1), V + 64 * 128, 128, tid);
    CP_COMMIT();
    float zacc[16][4];
#pragma unroll
    for (int t = 0; t < 16; t++) { zacc[t][0] = zacc[t][1] = zacc[t][2] = zacc[t][3] = 0.f; }
    for (int i = 0; i < 64; i++) {
        const int b = i & 1;
        CP_WAIT1();
        __syncthreads();
#pragma unroll
        for (int kk = 0; kk < 4; kk++) {
            uint32_t a0, a1, a2, a3;   // A-frags: Pt^T tile (warp's 16 n-rows, k=m)
            ldsm4t(lm_addrB(sb + PV_P(b), 136, kk * 16, warp * 16, lane), a0, a1, a2, a3);
#pragma unroll
            for (int et = 0; et < 8; et++) {
                uint32_t b0, b1, b2, b3;
                ldsm4t(lm_addrA(sb + PV_V(b), 136, kk * 16, et * 16, lane), b0, b1, b2, b3);
                mma16816(zacc[2 * et], a0, a1, a2, a3, b0, b1);
                mma16816(zacc[2 * et + 1], a0, a1, a2, a3, b2, b3);
            }
        }
        __syncthreads();
        if (i < 62) {
            cpaB(sb + PV_P(b), P + (size_t)(i + 2) * 64 * 4096, 4096, tid);
            cpaB(sb + PV_V(b), V + (size_t)(i + 2) * 64 * 128, 128, tid);
        }
        CP_COMMIT();
    }
#pragma unroll
    for (int t = 0; t < 16; t++) {
        int col = h * 128 + t * 8 + (lane & 3) * 2;
        int row = n0 + warp * 16 + (lane >> 2);
        *(float2*)&out[(size_t)row * 1024 + col] =
            make_float2(sigmoidf_(zacc[t][0]), sigmoidf_(zacc[t][1]));
        *(float2*)&out[(size_t)(row + 8) * 1024 + col] =
            make_float2(sigmoidf_(zacc[t][2]), sigmoidf_(zacc[t][3]));
    }
}

// ---------------- launch ----------------
extern "C" void kernel_launch(void* const* d_in, const int* in_sizes, int n_in,
                              void* d_out, int out_size) {
    const float* X  = (const float*)d_in[0];
    const float* Wq = (const float*)d_in[1];
    const float* bq = (const float*)d_in[2];
    const float* Wk = (const float*)d_in[3];
    const float* bk = (const float*)d_in[4];
    const float* Wv = (const float*)d_in[5];
    const float* bv = (const float*)d_in[6];
    float* out = (float*)d_out;

    cudaFuncSetAttribute(proj_kernel, cudaFuncAttributeMaxDynamicSharedMemorySize, 65536);
    cudaFuncSetAttribute(scoreP_kernel, cudaFuncAttributeMaxDynamicSharedMemorySize, 66048);
    cudaFuncSetAttribute(pv_kernel, cudaFuncAttributeMaxDynamicSharedMemorySize, 69632);

    cvtX_kernel<<<1024, 256>>>(X);
    cvtW_kernel<<<dim3(16, 2, 24), 256>>>(Wq, Wk, Wv);
    proj_kernel<<<dim3(32, 24), 256, 65536>>>(bq, bk, bv);
    scoreP_kernel<<<dim3(32, 8), 256, 66048>>>();
    pv_kernel<<<dim3(32, 8), 256, 69632>>>(out);
}

// round 10
// speedup vs baseline: 1.1432x; 1.1197x over previous
#include <cuda_runtime.h>
#include <cuda_bf16.h>
#include <cuda_fp8.h>
#include <cstdint>

#define SCALE_F 0.08838834764831845f
#define SW128(x) ((x) ^ (((x) >> 3) & 0x70))

// ---------------- scratch ----------------
__device__ uint8_t       g_Xf8[4096 * 1024];        // X e4m3 [n][d]
__device__ uint8_t       g_Wt8[24 * 128 * 1024];    // W e4m3 transposed [g][e][d]
__device__ uint8_t       g_Qf8[8 * 4096 * 128];     // Q e4m3 [h][n][e]
__device__ uint8_t       g_Kf8[8 * 4096 * 128];     // K e4m3 [h][m][e]
__device__ float         g_Vf[8 * 4096 * 128];      // V f32  [h][m][e]
__device__ __nv_bfloat16 g_Vs[8 * 4096 * 128];      // V/colsum bf16
__device__ __nv_bfloat16 g_Pt[8ull * 4096 * 4096];  // P^T = exp(scale*S)[h][m][n]

// ---------------- helpers ----------------
__device__ __forceinline__ uint32_t smem_u32(const void* p) {
    return (uint32_t)__cvta_generic_to_shared(p);
}
__device__ __forceinline__ uint32_t pack_bf2(float lo, float hi) {
    __nv_bfloat162 p = __floats2bfloat162_rn(lo, hi);
    return *reinterpret_cast<uint32_t*>(&p);
}
__device__ __forceinline__ float sigmoidf_(float x) { return 1.0f / (1.0f + __expf(-x)); }
__device__ __forceinline__ uint16_t f8x2(float a, float b) {
    return (uint16_t)__nv_cvt_float2_to_fp8x2(make_float2(a, b), __NV_SATFINITE, __NV_E4M3);
}

#define CPA16(s, g) asm volatile("cp.async.cg.shared.global [%0], [%1], 16;" :: "r"(s), "l"(g))
#define CP_COMMIT() asm volatile("cp.async.commit_group;" ::: "memory")
#define CP_WAIT1()  asm volatile("cp.async.wait_group 1;" ::: "memory")

__device__ __forceinline__ void ldsm4(uint32_t a, uint32_t& r0, uint32_t& r1, uint32_t& r2, uint32_t& r3) {
    asm volatile("ldmatrix.sync.aligned.m8n8.x4.shared.b16 {%0,%1,%2,%3}, [%4];"
                 : "=r"(r0), "=r"(r1), "=r"(r2), "=r"(r3) : "r"(a));
}
__device__ __forceinline__ void ldsm4t(uint32_t a, uint32_t& r0, uint32_t& r1, uint32_t& r2, uint32_t& r3) {
    asm volatile("ldmatrix.sync.aligned.m8n8.x4.trans.shared.b16 {%0,%1,%2,%3}, [%4];"
                 : "=r"(r0), "=r"(r1), "=r"(r2), "=r"(r3) : "r"(a));
}
__device__ __forceinline__ void mma16816(float c[4], uint32_t a0, uint32_t a1, uint32_t a2, uint32_t a3,
                                         uint32_t b0, uint32_t b1) {
    asm volatile("mma.sync.aligned.m16n8k16.row.col.f32.bf16.bf16.f32 "
        "{%0,%1,%2,%3},{%4,%5,%6,%7},{%8,%9},{%0,%1,%2,%3};"
        : "+f"(c[0]), "+f"(c[1]), "+f"(c[2]), "+f"(c[3])
        : "r"(a0), "r"(a1), "r"(a2), "r"(a3), "r"(b0), "r"(b1));
}
__device__ __forceinline__ void mma_f8(float c[4], uint32_t a0, uint32_t a1, uint32_t a2, uint32_t a3,
                                       uint32_t b0, uint32_t b1) {
    asm volatile("mma.sync.aligned.m16n8k32.row.col.f32.e4m3.e4m3.f32 "
        "{%0,%1,%2,%3},{%4,%5,%6,%7},{%8,%9},{%0,%1,%2,%3};"
        : "+f"(c[0]), "+f"(c[1]), "+f"(c[2]), "+f"(c[3])
        : "r"(a0), "r"(a1), "r"(a2), "r"(a3), "r"(b0), "r"(b1));
}

// fp8 swizzled tile (rows x 128B) ldmatrix addressing: kk = 32-byte k-step
__device__ __forceinline__ uint32_t lmA8(uint32_t base, int r0, int kk, int lane) {
    int r = r0 + (lane & 7) + ((lane >> 3) & 1) * 8;
    int c16 = kk * 2 + (lane >> 4);
    return base + SW128((uint32_t)((r << 7) + (c16 << 4)));
}
__device__ __forceinline__ uint32_t lmB8(uint32_t base, int r0, int kk, int lane) {
    int r = r0 + (lane & 7) + (lane >> 4) * 8;
    int c16 = kk * 2 + ((lane >> 3) & 1);
    return base + SW128((uint32_t)((r << 7) + (c16 << 4)));
}
// bf16 linear tile (ld elems): pattern A (B-frags via trans)
__device__ __forceinline__ uint32_t lm_addrA(uint32_t base, int ld, int row0, int col0, int lane) {
    int r = row0 + (lane & 7) + ((lane >> 3) & 1) * 8;
    int c = col0 + (lane >> 4) * 8;
    return base + (uint32_t)(r * ld + c) * 2u;
}
// bf16 linear tile: pattern B (A-frags from [k][n] storage via trans)
__device__ __forceinline__ uint32_t lm_addrB(uint32_t base, int ld, int row0, int col0, int lane) {
    int r = row0 + (lane & 7) + (lane >> 4) * 8;
    int c = col0 + ((lane >> 3) & 1) * 8;
    return base + (uint32_t)(r * ld + c) * 2u;
}

// loaders (256-thread CTAs)
__device__ __forceinline__ void cpa8(uint32_t dst, const uint8_t* src, int ldb, int rows, int tid) {
    for (int o = tid; o < rows * 8; o += 256) {
        int r = o >> 3, c = o & 7;
        CPA16(dst + SW128((uint32_t)((r << 7) + (c << 4))), src + (size_t)r * ldb + c * 16);
    }
}
// 64 x 128 bf16, global row stride ldel elems -> smem 272B rows
__device__ __forceinline__ void cpaB(uint32_t dst, const __nv_bfloat16* src, int ldel, int tid) {
    for (int o = tid; o < 1024; o += 256) {
        int r = o >> 4, c = o & 15;
        CPA16(dst + (uint32_t)(r * 272 + c * 16), (const char*)(src + (size_t)r * ldel) + c * 16);
    }
}

// ---------------- cvt X -> fp8 ----------------
__global__ void cvtX_kernel(const float* __restrict__ X) {
    int st = gridDim.x * blockDim.x;
    for (int o = blockIdx.x * blockDim.x + threadIdx.x; o < 1048576; o += st) {
        float4 v = ((const float4*)X)[o];
        ((uint32_t*)g_Xf8)[o] = (uint32_t)f8x2(v.x, v.y) | ((uint32_t)f8x2(v.z, v.w) << 16);
    }
}

// ---------------- cvt W -> fp8 transposed [g][e][d] ----------------
__global__ __launch_bounds__(256) void cvtW_kernel(const float* __restrict__ Wq,
                                                   const float* __restrict__ Wk,
                                                   const float* __restrict__ Wv) {
    __shared__ uint8_t t[64][96];
    const int g = blockIdx.z, d0 = blockIdx.x * 64, e0 = blockIdx.y * 64;
    const float* W = (g < 8 ? Wq : g < 16 ? Wk : Wv) + (size_t)(g & 7) * 131072;
    for (int o = threadIdx.x; o < 1024; o += 256) {
        int i = o >> 4, j4 = (o & 15) * 4;
        float4 v = *(const float4*)&W[(size_t)(d0 + i) * 128 + e0 + j4];
        t[j4 + 0][i] = (uint8_t)__nv_cvt_float_to_fp8(v.x, __NV_SATFINITE, __NV_E4M3);
        t[j4 + 1][i] = (uint8_t)__nv_cvt_float_to_fp8(v.y, __NV_SATFINITE, __NV_E4M3);
        t[j4 + 2][i] = (uint8_t)__nv_cvt_float_to_fp8(v.z, __NV_SATFINITE, __NV_E4M3);
        t[j4 + 3][i] = (uint8_t)__nv_cvt_float_to_fp8(v.w, __NV_SATFINITE, __NV_E4M3);
    }
    __syncthreads();
    for (int o = threadIdx.x; o < 256; o += 256) {
        int r = o >> 2, c = (o & 3) * 16;
        *(uint4*)&g_Wt8[(size_t)g * 131072 + (size_t)(e0 + r) * 1024 + d0 + c] = *(uint4*)&t[r][c];
    }
}

// ---------------- proj: C = X @ W_g + b (fp8 mma, k=1024) ----------------
#define PJ_A(b) ((b) * 16384)
#define PJ_B(b) (32768 + (b) * 16384)
__global__ __launch_bounds__(256, 2) void proj_kernel(const float* __restrict__ bq,
                                                      const float* __restrict__ bk,
                                                      const float* __restrict__ bv) {
    extern __shared__ char sm[];
    const uint32_t sb = smem_u32(sm);
    const int g = blockIdx.y, n0 = blockIdx.x * 128;
    const int tid = threadIdx.x, lane = tid & 31, warp = tid >> 5;
    const uint8_t* Xp = g_Xf8 + (size_t)n0 * 1024;
    const uint8_t* Wp = g_Wt8 + (size_t)g * 131072;
    cpa8(sb + PJ_A(0), Xp, 1024, 128, tid);
    cpa8(sb + PJ_B(0), Wp, 1024, 128, tid);
    CP_COMMIT();
    cpa8(sb + PJ_A(1), Xp + 128, 1024, 128, tid);
    cpa8(sb + PJ_B(1), Wp + 128, 1024, 128, tid);
    CP_COMMIT();
    float acc[16][4];
#pragma unroll
    for (int t = 0; t < 16; t++) { acc[t][0] = acc[t][1] = acc[t][2] = acc[t][3] = 0.f; }
    for (int i = 0; i < 8; i++) {
        const int b = i & 1;
        CP_WAIT1();
        __syncthreads();
#pragma unroll
        for (int kk = 0; kk < 4; kk++) {
            uint32_t a0, a1, a2, a3;
            ldsm4(lmA8(sb + PJ_A(b), warp * 16, kk, lane), a0, a1, a2, a3);
#pragma unroll
            for (int nt = 0; nt < 8; nt++) {
                uint32_t b0, b1, b2, b3;
                ldsm4(lmB8(sb + PJ_B(b), nt * 16, kk, lane), b0, b1, b2, b3);
                mma_f8(acc[2 * nt], a0, a1, a2, a3, b0, b1);
                mma_f8(acc[2 * nt + 1], a0, a1, a2, a3, b2, b3);
            }
        }
        __syncthreads();
        if (i < 6) {
            cpa8(sb + PJ_A(b), Xp + (i + 2) * 128, 1024, 128, tid);
            cpa8(sb + PJ_B(b), Wp + (i + 2) * 128, 1024, 128, tid);
        }
        CP_COMMIT();
    }
    const int h = g & 7, qkv = g >> 3;
    const float* bias = (qkv == 0 ? bq : qkv == 1 ? bk : bv) + h * 128;
#pragma unroll
    for (int t = 0; t < 16; t++) {
        int col = t * 8 + (lane & 3) * 2, row = n0 + warp * 16 + (lane >> 2);
        float v0 = acc[t][0] + bias[col], v1 = acc[t][1] + bias[col + 1];
        float v2 = acc[t][2] + bias[col], v3 = acc[t][3] + bias[col + 1];
        int o0 = (h * 4096 + row) * 128 + col, o1 = (h * 4096 + row + 8) * 128 + col;
        if (qkv == 0) {
            *(uint16_t*)&g_Qf8[o0] = f8x2(v0, v1); *(uint16_t*)&g_Qf8[o1] = f8x2(v2, v3);
        } else if (qkv == 1) {
            *(uint16_t*)&g_Kf8[o0] = f8x2(v0, v1); *(uint16_t*)&g_Kf8[o1] = f8x2(v2, v3);
        } else {
            *(float2*)&g_Vf[o0] = make_float2(v0, v1); *(float2*)&g_Vf[o1] = make_float2(v2, v3);
        }
    }
}

// ---- scoreP: m-tile 128, grid (32,8). R7 loop body (best measured) + fused Vs epilogue.
// S'[m][n]=K.Q^T fp8; P=exp -> g_Pt bf16; CTA owns its m-rows -> colsum complete ->
// Vs = V/colsum written here (no scalev kernel).
#define CS_K 0
#define CS_Q(b) (16384 + (b) * 16384)
#define CS_CS 49152
__global__ __launch_bounds__(256, 2) void scoreP_kernel() {
    extern __shared__ char sm[];
    const uint32_t sb = smem_u32(sm);
    float* cs = (float*)(sm + CS_CS);
    const int h = blockIdx.y, m0 = blockIdx.x * 128;
    const int tid = threadIdx.x, lane = tid & 31, warp = tid >> 5;
    const uint8_t* K = g_Kf8 + (size_t)h * 524288 + (size_t)m0 * 128;
    const uint8_t* Q = g_Qf8 + (size_t)h * 524288;
    cpa8(sb + CS_K, K, 128, 128, tid);
    cpa8(sb + CS_Q(0), Q, 128, 128, tid);
    CP_COMMIT();
    cpa8(sb + CS_Q(1), Q + 16384, 128, 128, tid);
    CP_COMMIT();
    CP_WAIT1();
    __syncthreads();
    uint32_t kf[4][4];                // persistent K fragments (warp's 16 m-rows)
#pragma unroll
    for (int kk = 0; kk < 4; kk++)
        ldsm4(lmA8(sb + CS_K, warp * 16, kk, lane), kf[kk][0], kf[kk][1], kf[kk][2], kf[kk][3]);
    float rs0 = 0.f, rs1 = 0.f;
    const size_t pr = (size_t)h * 16777216 + (size_t)(m0 + warp * 16 + (lane >> 2)) * 4096
                      + (size_t)((lane & 3) * 2);
    for (int i = 0; i < 32; i++) {
        const int b = i & 1;
        CP_WAIT1();
        __syncthreads();
#pragma unroll
        for (int hf = 0; hf < 2; hf++) {
            float sacc[8][4];
#pragma unroll
            for (int t = 0; t < 8; t++) { sacc[t][0] = sacc[t][1] = sacc[t][2] = sacc[t][3] = 0.f; }
#pragma unroll
            for (int kk = 0; kk < 4; kk++) {
#pragma unroll
                for (int nt = 0; nt < 4; nt++) {
                    uint32_t b0, b1, b2, b3;
                    ldsm4(lmB8(sb + CS_Q(b), hf * 64 + nt * 16, kk, lane), b0, b1, b2, b3);
                    mma_f8(sacc[2 * nt], kf[kk][0], kf[kk][1], kf[kk][2], kf[kk][3], b0, b1);
                    mma_f8(sacc[2 * nt + 1], kf[kk][0], kf[kk][1], kf[kk][2], kf[kk][3], b2, b3);
                }
            }
            const size_t pb = pr + (size_t)i * 128 + hf * 64;
#pragma unroll
            for (int t = 0; t < 8; t++) {
                float e0 = __expf(sacc[t][0] * SCALE_F), e1 = __expf(sacc[t][1] * SCALE_F);
                float e2 = __expf(sacc[t][2] * SCALE_F), e3 = __expf(sacc[t][3] * SCALE_F);
                rs0 += e0 + e1;
                rs1 += e2 + e3;
                *(uint32_t*)&g_Pt[pb + t * 8]            = pack_bf2(e0, e1);
                *(uint32_t*)&g_Pt[pb + 8 * 4096 + t * 8] = pack_bf2(e2, e3);
            }
        }
        __syncthreads();
        if (i < 30) cpa8(sb + CS_Q(b), Q + (size_t)(i + 2) * 16384, 128, 128, tid);
        CP_COMMIT();
    }
    // colsum (complete for this CTA's 128 m-rows) -> smem
    rs0 += __shfl_xor_sync(0xffffffffu, rs0, 1);
    rs0 += __shfl_xor_sync(0xffffffffu, rs0, 2);
    rs1 += __shfl_xor_sync(0xffffffffu, rs1, 1);
    rs1 += __shfl_xor_sync(0xffffffffu, rs1, 2);
    if ((lane & 3) == 0) {
        cs[warp * 16 + (lane >> 2)]     = rs0;
        cs[warp * 16 + 8 + (lane >> 2)] = rs1;
    }
    __syncthreads();
    // fused scalev: Vs[m][e] = V[m][e] / colsum[m] (bf16)
    for (int o = tid; o < 4096; o += 256) {
        int row = o >> 5, e4 = (o & 31) * 4;
        size_t gi = (size_t)(h * 4096 + m0 + row) * 128 + e4;
        float4 v = *(const float4*)&g_Vf[gi];
        float inv = __frcp_rn(cs[row]);
        uint2 u;
        u.x = pack_bf2(v.x * inv, v.y * inv);
        u.y = pack_bf2(v.z * inv, v.w * inv);
        *(uint2*)&g_Vs[gi] = u;
    }
}

// ---- pv: n-tile 128, warps 4(n:32 rows) x 2(e:64). Z = Pt^T @ Vs; sigmoid. ----
// B-frags (V) shared across the warp's two n-subtiles: 24 ldsm/iter (was 36).
#define PV_P(b) ((b) * 17408)
#define PV_V(b) (34816 + (b) * 17408)
__global__ __launch_bounds__(256, 2) void pv_kernel(float* __restrict__ out) {
    extern __shared__ char sm[];
    const uint32_t sb = smem_u32(sm);
    const int h = blockIdx.y, n0 = blockIdx.x * 128;
    const int tid = threadIdx.x, lane = tid & 31, warp = tid >> 5;
    const int wn = warp & 3, we = warp >> 2;
    const __nv_bfloat16* P = g_Pt + (size_t)h * 16777216 + n0;   // rows m (stride 4096)
    const __nv_bfloat16* V = g_Vs + (size_t)h * 524288;          // rows m (stride 128)
    cpaB(sb + PV_P(0), P, 4096, tid);
    cpaB(sb + PV_V(0), V, 128, tid);
    CP_COMMIT();
    cpaB(sb + PV_P(1), P + (size_t)64 * 4096, 4096, tid);
    cpaB(sb + PV_V(1), V + 64 * 128, 128, tid);
    CP_COMMIT();
    float zacc[16][4];                 // [s*8 + 2*et(+1)] : s in n-subtile, et in e
#pragma unroll
    for (int t = 0; t < 16; t++) { zacc[t][0] = zacc[t][1] = zacc[t][2] = zacc[t][3] = 0.f; }
    for (int i = 0; i < 64; i++) {
        const int b = i & 1;
        CP_WAIT1();
        __syncthreads();
#pragma unroll
        for (int kk = 0; kk < 4; kk++) {
            uint32_t a[2][4];          // A-frags: P^T, warp's two 16-row n-subtiles
#pragma unroll
            for (int s = 0; s < 2; s++)
                ldsm4t(lm_addrB(sb + PV_P(b), 136, kk * 16, wn * 32 + s * 16, lane),
                       a[s][0], a[s][1], a[s][2], a[s][3]);
#pragma unroll
            for (int et = 0; et < 4; et++) {
                uint32_t b0, b1, b2, b3;
                ldsm4t(lm_addrA(sb + PV_V(b), 136, kk * 16, we * 64 + et * 16, lane), b0, b1, b2, b3);
#pragma unroll
                for (int s = 0; s < 2; s++) {
                    mma16816(zacc[s * 8 + 2 * et],     a[s][0], a[s][1], a[s][2], a[s][3], b0, b1);
                    mma16816(zacc[s * 8 + 2 * et + 1], a[s][0], a[s][1], a[s][2], a[s][3], b2, b3);
                }
            }
        }
        __syncthreads();
        if (i < 62) {
            cpaB(sb + PV_P(b), P + (size_t)(i + 2) * 64 * 4096, 4096, tid);
            cpaB(sb + PV_V(b), V + (size_t)(i + 2) * 64 * 128, 128, tid);
        }
        CP_COMMIT();
    }
#pragma unroll
    for (int s = 0; s < 2; s++) {
#pragma unroll
        for (int t = 0; t < 8; t++) {
            int col = h * 128 + we * 64 + t * 8 + (lane & 3) * 2;
            int row = n0 + wn * 32 + s * 16 + (lane >> 2);
            *(float2*)&out[(size_t)row * 1024 + col] =
                make_float2(sigmoidf_(zacc[s * 8 + t][0]), sigmoidf_(zacc[s * 8 + t][1]));
            *(float2*)&out[(size_t)(row + 8) * 1024 + col] =
                make_float2(sigmoidf_(zacc[s * 8 + t][2]), sigmoidf_(zacc[s * 8 + t][3]));
        }
    }
}

// ---------------- launch ----------------
extern "C" void kernel_launch(void* const* d_in, const int* in_sizes, int n_in,
                              void* d_out, int out_size) {
    const float* X  = (const float*)d_in[0];
    const float* Wq = (const float*)d_in[1];
    const float* bq = (const float*)d_in[2];
    const float* Wk = (const float*)d_in[3];
    const float* bk = (const float*)d_in[4];
    const float* Wv = (const float*)d_in[5];
    const float* bv = (const float*)d_in[6];
    float* out = (float*)d_out;

    cudaFuncSetAttribute(proj_kernel, cudaFuncAttributeMaxDynamicSharedMemorySize, 65536);
    cudaFuncSetAttribute(scoreP_kernel, cudaFuncAttributeMaxDynamicSharedMemorySize, 49664);
    cudaFuncSetAttribute(pv_kernel, cudaFuncAttributeMaxDynamicSharedMemorySize, 69632);

    cvtX_kernel<<<1024, 256>>>(X);
    cvtW_kernel<<<dim3(16, 2, 24), 256>>>(Wq, Wk, Wv);
    proj_kernel<<<dim3(32, 24), 256, 65536>>>(bq, bk, bv);
    scoreP_kernel<<<dim3(32, 8), 256, 49664>>>();
    pv_kernel<<<dim3(32, 8), 256, 69632>>>(out);
}

// round 11
// speedup vs baseline: 1.1927x; 1.0433x over previous
#include <cuda_runtime.h>
#include <cuda_bf16.h>
#include <cuda_fp8.h>
#include <cstdint>

#define SCALE_F 0.08838834764831845f
// SCALE * log2(e): folded into K at fp8-conversion time so P = exp2(S) directly.
#define KSCALE_F 0.12752536889111582f
#define SW128(x) ((x) ^ (((x) >> 3) & 0x70))

// ---------------- scratch ----------------
__device__ uint8_t       g_Xf8[4096 * 1024];        // X e4m3 [n][d]
__device__ uint8_t       g_Wt8[24 * 128 * 1024];    // W e4m3 transposed [g][e][d]
__device__ uint8_t       g_Qf8[8 * 4096 * 128];     // Q e4m3 [h][n][e]
__device__ uint8_t       g_Kf8[8 * 4096 * 128];     // K*KSCALE e4m3 [h][m][e]
__device__ float         g_Vf[8 * 4096 * 128];      // V f32  [h][m][e]
__device__ __nv_bfloat16 g_Vs[8 * 4096 * 128];      // V/colsum bf16
__device__ __nv_bfloat16 g_Pt[8ull * 4096 * 4096];  // P^T = exp2(S')[h][m][n]

// ---------------- helpers ----------------
__device__ __forceinline__ uint32_t smem_u32(const void* p) {
    return (uint32_t)__cvta_generic_to_shared(p);
}
__device__ __forceinline__ uint32_t pack_bf2(float lo, float hi) {
    __nv_bfloat162 p = __floats2bfloat162_rn(lo, hi);
    return *reinterpret_cast<uint32_t*>(&p);
}
__device__ __forceinline__ float sigmoidf_(float x) { return 1.0f / (1.0f + __expf(-x)); }
__device__ __forceinline__ float ex2_(float x) {
    float r;
    asm("ex2.approx.f32 %0, %1;" : "=f"(r) : "f"(x));
    return r;
}
__device__ __forceinline__ uint16_t f8x2(float a, float b) {
    return (uint16_t)__nv_cvt_float2_to_fp8x2(make_float2(a, b), __NV_SATFINITE, __NV_E4M3);
}

#define CPA16(s, g) asm volatile("cp.async.cg.shared.global [%0], [%1], 16;" :: "r"(s), "l"(g))
#define CP_COMMIT() asm volatile("cp.async.commit_group;" ::: "memory")
#define CP_WAIT1()  asm volatile("cp.async.wait_group 1;" ::: "memory")

__device__ __forceinline__ void ldsm4(uint32_t a, uint32_t& r0, uint32_t& r1, uint32_t& r2, uint32_t& r3) {
    asm volatile("ldmatrix.sync.aligned.m8n8.x4.shared.b16 {%0,%1,%2,%3}, [%4];"
                 : "=r"(r0), "=r"(r1), "=r"(r2), "=r"(r3) : "r"(a));
}
__device__ __forceinline__ void ldsm4t(uint32_t a, uint32_t& r0, uint32_t& r1, uint32_t& r2, uint32_t& r3) {
    asm volatile("ldmatrix.sync.aligned.m8n8.x4.trans.shared.b16 {%0,%1,%2,%3}, [%4];"
                 : "=r"(r0), "=r"(r1), "=r"(r2), "=r"(r3) : "r"(a));
}
__device__ __forceinline__ void mma16816(float c[4], uint32_t a0, uint32_t a1, uint32_t a2, uint32_t a3,
                                         uint32_t b0, uint32_t b1) {
    asm volatile("mma.sync.aligned.m16n8k16.row.col.f32.bf16.bf16.f32 "
        "{%0,%1,%2,%3},{%4,%5,%6,%7},{%8,%9},{%0,%1,%2,%3};"
        : "+f"(c[0]), "+f"(c[1]), "+f"(c[2]), "+f"(c[3])
        : "r"(a0), "r"(a1), "r"(a2), "r"(a3), "r"(b0), "r"(b1));
}
__device__ __forceinline__ void mma_f8(float c[4], uint32_t a0, uint32_t a1, uint32_t a2, uint32_t a3,
                                       uint32_t b0, uint32_t b1) {
    asm volatile("mma.sync.aligned.m16n8k32.row.col.f32.e4m3.e4m3.f32 "
        "{%0,%1,%2,%3},{%4,%5,%6,%7},{%8,%9},{%0,%1,%2,%3};"
        : "+f"(c[0]), "+f"(c[1]), "+f"(c[2]), "+f"(c[3])
        : "r"(a0), "r"(a1), "r"(a2), "r"(a3), "r"(b0), "r"(b1));
}

// fp8 swizzled tile (rows x 128B) ldmatrix addressing: kk = 32-byte k-step
__device__ __forceinline__ uint32_t lmA8(uint32_t base, int r0, int kk, int lane) {
    int r = r0 + (lane & 7) + ((lane >> 3) & 1) * 8;
    int c16 = kk * 2 + (lane >> 4);
    return base + SW128((uint32_t)((r << 7) + (c16 << 4)));
}
__device__ __forceinline__ uint32_t lmB8(uint32_t base, int r0, int kk, int lane) {
    int r = r0 + (lane & 7) + (lane >> 4) * 8;
    int c16 = kk * 2 + ((lane >> 3) & 1);
    return base + SW128((uint32_t)((r << 7) + (c16 << 4)));
}
// bf16 linear tile (ld elems): pattern A (B-frags via trans)
__device__ __forceinline__ uint32_t lm_addrA(uint32_t base, int ld, int row0, int col0, int lane) {
    int r = row0 + (lane & 7) + ((lane >> 3) & 1) * 8;
    int c = col0 + (lane >> 4) * 8;
    return base + (uint32_t)(r * ld + c) * 2u;
}
// bf16 linear tile: pattern B (A-frags from [k][n] storage via trans)
__device__ __forceinline__ uint32_t lm_addrB(uint32_t base, int ld, int row0, int col0, int lane) {
    int r = row0 + (lane & 7) + (lane >> 4) * 8;
    int c = col0 + ((lane >> 3) & 1) * 8;
    return base + (uint32_t)(r * ld + c) * 2u;
}

// loaders (256-thread CTAs)
__device__ __forceinline__ void cpa8(uint32_t dst, const uint8_t* src, int ldb, int rows, int tid) {
    for (int o = tid; o < rows * 8; o += 256) {
        int r = o >> 3, c = o & 7;
        CPA16(dst + SW128((uint32_t)((r << 7) + (c << 4))), src + (size_t)r * ldb + c * 16);
    }
}
// 64 x 128 bf16, global row stride ldel elems -> smem 272B rows
__device__ __forceinline__ void cpaB(uint32_t dst, const __nv_bfloat16* src, int ldel, int tid) {
    for (int o = tid; o < 1024; o += 256) {
        int r = o >> 4, c = o & 15;
        CPA16(dst + (uint32_t)(r * 272 + c * 16), (const char*)(src + (size_t)r * ldel) + c * 16);
    }
}

// ---------------- cvt X -> fp8 ----------------
__global__ void cvtX_kernel(const float* __restrict__ X) {
    int st = gridDim.x * blockDim.x;
    for (int o = blockIdx.x * blockDim.x + threadIdx.x; o < 1048576; o += st) {
        float4 v = ((const float4*)X)[o];
        ((uint32_t*)g_Xf8)[o] = (uint32_t)f8x2(v.x, v.y) | ((uint32_t)f8x2(v.z, v.w) << 16);
    }
}

// ---------------- cvt W -> fp8 transposed [g][e][d] ----------------
__global__ __launch_bounds__(256) void cvtW_kernel(const float* __restrict__ Wq,
                                                   const float* __restrict__ Wk,
                                                   const float* __restrict__ Wv) {
    __shared__ uint8_t t[64][96];
    const int g = blockIdx.z, d0 = blockIdx.x * 64, e0 = blockIdx.y * 64;
    const float* W = (g < 8 ? Wq : g < 16 ? Wk : Wv) + (size_t)(g & 7) * 131072;
    for (int o = threadIdx.x; o < 1024; o += 256) {
        int i = o >> 4, j4 = (o & 15) * 4;
        float4 v = *(const float4*)&W[(size_t)(d0 + i) * 128 + e0 + j4];
        t[j4 + 0][i] = (uint8_t)__nv_cvt_float_to_fp8(v.x, __NV_SATFINITE, __NV_E4M3);
        t[j4 + 1][i] = (uint8_t)__nv_cvt_float_to_fp8(v.y, __NV_SATFINITE, __NV_E4M3);
        t[j4 + 2][i] = (uint8_t)__nv_cvt_float_to_fp8(v.z, __NV_SATFINITE, __NV_E4M3);
        t[j4 + 3][i] = (uint8_t)__nv_cvt_float_to_fp8(v.w, __NV_SATFINITE, __NV_E4M3);
    }
    __syncthreads();
    for (int o = threadIdx.x; o < 256; o += 256) {
        int r = o >> 2, c = (o & 3) * 16;
        *(uint4*)&g_Wt8[(size_t)g * 131072 + (size_t)(e0 + r) * 1024 + d0 + c] = *(uint4*)&t[r][c];
    }
}

// ---------------- proj: C = X @ W_g + b (fp8 mma, k=1024) ----------------
// K outputs (qkv==1) are pre-scaled by KSCALE so scoreP's exp is a bare EX2.
#define PJ_A(b) ((b) * 16384)
#define PJ_B(b) (32768 + (b) * 16384)
__global__ __launch_bounds__(256, 2) void proj_kernel(const float* __restrict__ bq,
                                                      const float* __restrict__ bk,
                                                      const float* __restrict__ bv) {
    extern __shared__ char sm[];
    const uint32_t sb = smem_u32(sm);
    const int g = blockIdx.y, n0 = blockIdx.x * 128;
    const int tid = threadIdx.x, lane = tid & 31, warp = tid >> 5;
    const uint8_t* Xp = g_Xf8 + (size_t)n0 * 1024;
    const uint8_t* Wp = g_Wt8 + (size_t)g * 131072;
    cpa8(sb + PJ_A(0), Xp, 1024, 128, tid);
    cpa8(sb + PJ_B(0), Wp, 1024, 128, tid);
    CP_COMMIT();
    cpa8(sb + PJ_A(1), Xp + 128, 1024, 128, tid);
    cpa8(sb + PJ_B(1), Wp + 128, 1024, 128, tid);
    CP_COMMIT();
    float acc[16][4];
#pragma unroll
    for (int t = 0; t < 16; t++) { acc[t][0] = acc[t][1] = acc[t][2] = acc[t][3] = 0.f; }
    for (int i = 0; i < 8; i++) {
        const int b = i & 1;
        CP_WAIT1();
        __syncthreads();
#pragma unroll
        for (int kk = 0; kk < 4; kk++) {
            uint32_t a0, a1, a2, a3;
            ldsm4(lmA8(sb + PJ_A(b), warp * 16, kk, lane), a0, a1, a2, a3);
#pragma unroll
            for (int nt = 0; nt < 8; nt++) {
                uint32_t b0, b1, b2, b3;
                ldsm4(lmB8(sb + PJ_B(b), nt * 16, kk, lane), b0, b1, b2, b3);
                mma_f8(acc[2 * nt], a0, a1, a2, a3, b0, b1);
                mma_f8(acc[2 * nt + 1], a0, a1, a2, a3, b2, b3);
            }
        }
        __syncthreads();
        if (i < 6) {
            cpa8(sb + PJ_A(b), Xp + (i + 2) * 128, 1024, 128, tid);
            cpa8(sb + PJ_B(b), Wp + (i + 2) * 128, 1024, 128, tid);
        }
        CP_COMMIT();
    }
    const int h = g & 7, qkv = g >> 3;
    const float* bias = (qkv == 0 ? bq : qkv == 1 ? bk : bv) + h * 128;
#pragma unroll
    for (int t = 0; t < 16; t++) {
        int col = t * 8 + (lane & 3) * 2, row = n0 + warp * 16 + (lane >> 2);
        float v0 = acc[t][0] + bias[col], v1 = acc[t][1] + bias[col + 1];
        float v2 = acc[t][2] + bias[col], v3 = acc[t][3] + bias[col + 1];
        int o0 = (h * 4096 + row) * 128 + col, o1 = (h * 4096 + row + 8) * 128 + col;
        if (qkv == 0) {
            *(uint16_t*)&g_Qf8[o0] = f8x2(v0, v1); *(uint16_t*)&g_Qf8[o1] = f8x2(v2, v3);
        } else if (qkv == 1) {
            *(uint16_t*)&g_Kf8[o0] = f8x2(v0 * KSCALE_F, v1 * KSCALE_F);
            *(uint16_t*)&g_Kf8[o1] = f8x2(v2 * KSCALE_F, v3 * KSCALE_F);
        } else {
            *(float2*)&g_Vf[o0] = make_float2(v0, v1); *(float2*)&g_Vf[o1] = make_float2(v2, v3);
        }
    }
}

// ---- scoreP: m-tile 128, grid (32,8). S'[m][n]=K'.Q^T fp8 (K' pre-scaled);
// P = exp2(S') -> g_Pt bf16 (bare EX2, no FMUL); colsum complete per CTA ->
// fused Vs = V/colsum epilogue.
#define CS_K 0
#define CS_Q(b) (16384 + (b) * 16384)
#define CS_CS 49152
__global__ __launch_bounds__(256, 2) void scoreP_kernel() {
    extern __shared__ char sm[];
    const uint32_t sb = smem_u32(sm);
    float* cs = (float*)(sm + CS_CS);
    const int h = blockIdx.y, m0 = blockIdx.x * 128;
    const int tid = threadIdx.x, lane = tid & 31, warp = tid >> 5;
    const uint8_t* K = g_Kf8 + (size_t)h * 524288 + (size_t)m0 * 128;
    const uint8_t* Q = g_Qf8 + (size_t)h * 524288;
    cpa8(sb + CS_K, K, 128, 128, tid);
    cpa8(sb + CS_Q(0), Q, 128, 128, tid);
    CP_COMMIT();
    cpa8(sb + CS_Q(1), Q + 16384, 128, 128, tid);
    CP_COMMIT();
    CP_WAIT1();
    __syncthreads();
    uint32_t kf[4][4];                // persistent K fragments (warp's 16 m-rows)
#pragma unroll
    for (int kk = 0; kk < 4; kk++)
        ldsm4(lmA8(sb + CS_K, warp * 16, kk, lane), kf[kk][0], kf[kk][1], kf[kk][2], kf[kk][3]);
    float rs0 = 0.f, rs1 = 0.f;
    const size_t pr = (size_t)h * 16777216 + (size_t)(m0 + warp * 16 + (lane >> 2)) * 4096
                      + (size_t)((lane & 3) * 2);
    for (int i = 0; i < 32; i++) {
        const int b = i & 1;
        CP_WAIT1();
        __syncthreads();
#pragma unroll
        for (int hf = 0; hf < 2; hf++) {
            float sacc[8][4];
#pragma unroll
            for (int t = 0; t < 8; t++) { sacc[t][0] = sacc[t][1] = sacc[t][2] = sacc[t][3] = 0.f; }
#pragma unroll
            for (int kk = 0; kk < 4; kk++) {
#pragma unroll
                for (int nt = 0; nt < 4; nt++) {
                    uint32_t b0, b1, b2, b3;
                    ldsm4(lmB8(sb + CS_Q(b), hf * 64 + nt * 16, kk, lane), b0, b1, b2, b3);
                    mma_f8(sacc[2 * nt], kf[kk][0], kf[kk][1], kf[kk][2], kf[kk][3], b0, b1);
                    mma_f8(sacc[2 * nt + 1], kf[kk][0], kf[kk][1], kf[kk][2], kf[kk][3], b2, b3);
                }
            }
            const size_t pb = pr + (size_t)i * 128 + hf * 64;
#pragma unroll
            for (int t = 0; t < 8; t++) {
                float e0 = ex2_(sacc[t][0]), e1 = ex2_(sacc[t][1]);
                float e2 = ex2_(sacc[t][2]), e3 = ex2_(sacc[t][3]);
                rs0 += e0 + e1;
                rs1 += e2 + e3;
                *(uint32_t*)&g_Pt[pb + t * 8]            = pack_bf2(e0, e1);
                *(uint32_t*)&g_Pt[pb + 8 * 4096 + t * 8] = pack_bf2(e2, e3);
            }
        }
        __syncthreads();
        if (i < 30) cpa8(sb + CS_Q(b), Q + (size_t)(i + 2) * 16384, 128, 128, tid);
        CP_COMMIT();
    }
    // colsum (complete for this CTA's 128 m-rows) -> smem
    rs0 += __shfl_xor_sync(0xffffffffu, rs0, 1);
    rs0 += __shfl_xor_sync(0xffffffffu, rs0, 2);
    rs1 += __shfl_xor_sync(0xffffffffu, rs1, 1);
    rs1 += __shfl_xor_sync(0xffffffffu, rs1, 2);
    if ((lane & 3) == 0) {
        cs[warp * 16 + (lane >> 2)]     = rs0;
        cs[warp * 16 + 8 + (lane >> 2)] = rs1;
    }
    __syncthreads();
    // fused scalev: Vs[m][e] = V[m][e] / colsum[m] (bf16)
    for (int o = tid; o < 4096; o += 256) {
        int row = o >> 5, e4 = (o & 31) * 4;
        size_t gi = (size_t)(h * 4096 + m0 + row) * 128 + e4;
        float4 v = *(const float4*)&g_Vf[gi];
        float inv = __frcp_rn(cs[row]);
        uint2 u;
        u.x = pack_bf2(v.x * inv, v.y * inv);
        u.y = pack_bf2(v.z * inv, v.w * inv);
        *(uint2*)&g_Vs[gi] = u;
    }
}

// ---- pv: n-tile 128, warps 4(n:32 rows) x 2(e:64). Z = Pt^T @ Vs; sigmoid. ----
#define PV_P(b) ((b) * 17408)
#define PV_V(b) (34816 + (b) * 17408)
__global__ __launch_bounds__(256, 2) void pv_kernel(float* __restrict__ out) {
    extern __shared__ char sm[];
    const uint32_t sb = smem_u32(sm);
    const int h = blockIdx.y, n0 = blockIdx.x * 128;
    const int tid = threadIdx.x, lane = tid & 31, warp = tid >> 5;
    const int wn = warp & 3, we = warp >> 2;
    const __nv_bfloat16* P = g_Pt + (size_t)h * 16777216 + n0;   // rows m (stride 4096)
    const __nv_bfloat16* V = g_Vs + (size_t)h * 524288;          // rows m (stride 128)
    cpaB(sb + PV_P(0), P, 4096, tid);
    cpaB(sb + PV_V(0), V, 128, tid);
    CP_COMMIT();
    cpaB(sb + PV_P(1), P + (size_t)64 * 4096, 4096, tid);
    cpaB(sb + PV_V(1), V + 64 * 128, 128, tid);
    CP_COMMIT();
    float zacc[16][4];                 // [s*8 + 2*et(+1)] : s in n-subtile, et in e
#pragma unroll
    for (int t = 0; t < 16; t++) { zacc[t][0] = zacc[t][1] = zacc[t][2] = zacc[t][3] = 0.f; }
    for (int i = 0; i < 64; i++) {
        const int b = i & 1;
        CP_WAIT1();
        __syncthreads();
#pragma unroll
        for (int kk = 0; kk < 4; kk++) {
            uint32_t a[2][4];          // A-frags: P^T, warp's two 16-row n-subtiles
#pragma unroll
            for (int s = 0; s < 2; s++)
                ldsm4t(lm_addrB(sb + PV_P(b), 136, kk * 16, wn * 32 + s * 16, lane),
                       a[s][0], a[s][1], a[s][2], a[s][3]);
#pragma unroll
            for (int et = 0; et < 4; et++) {
                uint32_t b0, b1, b2, b3;
                ldsm4t(lm_addrA(sb + PV_V(b), 136, kk * 16, we * 64 + et * 16, lane), b0, b1, b2, b3);
#pragma unroll
                for (int s = 0; s < 2; s++) {
                    mma16816(zacc[s * 8 + 2 * et],     a[s][0], a[s][1], a[s][2], a[s][3], b0, b1);
                    mma16816(zacc[s * 8 + 2 * et + 1], a[s][0], a[s][1], a[s][2], a[s][3], b2, b3);
                }
            }
        }
        __syncthreads();
        if (i < 62) {
            cpaB(sb + PV_P(b), P + (size_t)(i + 2) * 64 * 4096, 4096, tid);
            cpaB(sb + PV_V(b), V + (size_t)(i + 2) * 64 * 128, 128, tid);
        }
        CP_COMMIT();
    }
#pragma unroll
    for (int s = 0; s < 2; s++) {
#pragma unroll
        for (int t = 0; t < 8; t++) {
            int col = h * 128 + we * 64 + t * 8 + (lane & 3) * 2;
            int row = n0 + wn * 32 + s * 16 + (lane >> 2);
            *(float2*)&out[(size_t)row * 1024 + col] =
                make_float2(sigmoidf_(zacc[s * 8 + t][0]), sigmoidf_(zacc[s * 8 + t][1]));
            *(float2*)&out[(size_t)(row + 8) * 1024 + col] =
                make_float2(sigmoidf_(zacc[s * 8 + t][2]), sigmoidf_(zacc[s * 8 + t][3]));
        }
    }
}

// ---------------- launch ----------------
extern "C" void kernel_launch(void* const* d_in, const int* in_sizes, int n_in,
                              void* d_out, int out_size) {
    const float* X  = (const float*)d_in[0];
    const float* Wq = (const float*)d_in[1];
    const float* bq = (const float*)d_in[2];
    const float* Wk = (const float*)d_in[3];
    const float* bk = (const float*)d_in[4];
    const float* Wv = (const float*)d_in[5];
    const float* bv = (const float*)d_in[6];
    float* out = (float*)d_out;

    cudaFuncSetAttribute(proj_kernel, cudaFuncAttributeMaxDynamicSharedMemorySize, 65536);
    cudaFuncSetAttribute(scoreP_kernel, cudaFuncAttributeMaxDynamicSharedMemorySize, 49664);
    cudaFuncSetAttribute(pv_kernel, cudaFuncAttributeMaxDynamicSharedMemorySize, 69632);

    cvtX_kernel<<<1024, 256>>>(X);
    cvtW_kernel<<<dim3(16, 2, 24), 256>>>(Wq, Wk, Wv);
    proj_kernel<<<dim3(32, 24), 256, 65536>>>(bq, bk, bv);
    scoreP_kernel<<<dim3(32, 8), 256, 49664>>>();
    pv_kernel<<<dim3(32, 8), 256, 69632>>>(out);
}